// round 14
// baseline (speedup 1.0000x reference)
#include <cuda_runtime.h>
#include <cuda_bf16.h>
#include <cuda_fp16.h>

#define Bb 128
#define Tt 256
#define Dd 1024
#define Hh 1024
#define Vv 1024
#define Ss 128
#define H3 3072
#define NBLK 296
#define PITCH 24
#define BV (Bb * Vv)

// ---------------- scratch (device globals; no cudaMalloc allowed) -----------
__device__ __align__(16) __nv_bfloat16 g_whb[(long)Bb * Tt * Hh];  // 67 MB bf16
__device__ __align__(16) __half g_hf16[(long)Bb * Tt * Dd];        // 67 MB fp16
__device__ __align__(16) float g_part_proj[4 * Bb * Hh];
__device__ __align__(16) float g_part_gi[4 * Bb * H3];   // 0,1=gi_y  2,3=gi_c
__device__ __align__(16) float g_part_gh[2 * Bb * H3];
__device__ __align__(16) float g_part_pre[2 * 8 * BV];   // [par][slot]: 0,1 ihc; 2-5 ihs; 6,7 hh
__device__ __align__(16) float g_s[Bb * Hh];
__device__ __align__(16) float g_scores[Bb * Tt];
__device__ unsigned g_bsync[Bb];

// split-bf16 mirrors: value = hi + lo
__device__ __align__(16) __nv_bfloat16 g_s_h[Bb * Hh], g_s_l[Bb * Hh];
__device__ __align__(16) __nv_bfloat16 g_c_h[Bb * Hh], g_c_l[Bb * Hh];
__device__ __align__(16) __nv_bfloat16 g_y_h[Bb * Hh], g_y_l[Bb * Hh];
// weights (split)
__device__ __align__(16) __nv_bfloat16 g_wsa_h[1024 * 1024], g_wsa_l[1024 * 1024];
__device__ __align__(16) __nv_bfloat16 g_gwh_h[3072 * 1024], g_gwh_l[3072 * 1024];
__device__ __align__(16) __nv_bfloat16 g_gwi_h[(long)3072 * 2048], g_gwi_l[(long)3072 * 2048];
__device__ __align__(16) __nv_bfloat16 g_rwi_h[(long)1024 * 2048], g_rwi_l[(long)1024 * 2048];
__device__ __align__(16) __nv_bfloat16 g_rwh_h[1024 * 1024], g_rwh_l[1024 * 1024];
__device__ __align__(16) __nv_bfloat16 g_wha_h[1024 * 1024], g_wha_l[1024 * 1024];
__device__ __align__(16) __nv_bfloat16 g_wis_h[1024 * 1024], g_wis_l[1024 * 1024];
__device__ __align__(16) __nv_bfloat16 g_h_h[(long)Bb * Tt * Dd], g_h_l[(long)Bb * Tt * Dd];

__device__ unsigned g_bar_count = 0;
__device__ unsigned g_bar_gen = 0;

// ---------------- math helpers -----------------------------------------------
__device__ __forceinline__ float ex2_approx(float x) {
    float r; asm("ex2.approx.ftz.f32 %0, %1;" : "=f"(r) : "f"(x)); return r;
}
__device__ __forceinline__ float rcp_approx(float x) {
    float r; asm("rcp.approx.ftz.f32 %0, %1;" : "=f"(r) : "f"(x)); return r;
}
__device__ __forceinline__ float exp_mufu(float x) {
    return ex2_approx(x * 1.4426950408889634f);
}
__device__ __forceinline__ float tanh_hw(float x) {
    float r; asm("tanh.approx.f32 %0, %1;" : "=f"(r) : "f"(x)); return r;
}
__device__ __forceinline__ float tanh_mufu(float x) {
    float ax = fabsf(x);
    float e  = ex2_approx(ax * -2.885390081777927f);
    float r  = rcp_approx(1.0f + e);
    float th = fmaf(-2.0f * e, r, 1.0f);
    return copysignf(th, x);
}
__device__ __forceinline__ float sigmoid_mufu(float x) {
    float e = ex2_approx(x * -1.4426950408889634f);
    return rcp_approx(1.0f + e);
}
__device__ __forceinline__ float warp_sum(float v) {
#pragma unroll
    for (int o = 16; o > 0; o >>= 1) v += __shfl_xor_sync(0xffffffffu, v, o);
    return v;
}
__device__ __forceinline__ float warp_max(float v) {
#pragma unroll
    for (int o = 16; o > 0; o >>= 1) v = fmaxf(v, __shfl_xor_sync(0xffffffffu, v, o));
    return v;
}
__device__ __forceinline__ void split_w(float v, __nv_bfloat16* hi, __nv_bfloat16* lo, long i) {
    __nv_bfloat16 hb = __float2bfloat16(v);
    hi[i] = hb;
    lo[i] = __float2bfloat16(v - __bfloat162float(hb));
}
// streaming load (cache-streaming / evict-first)
__device__ __forceinline__ uint4 ldg_ef(const uint4* p) {
    return __ldcs(p);
}
// 8-wide tanh-dot for one wh row chunk (HW tanh)
__device__ __forceinline__ float score8(uint4 u, float4 p0, float4 p1, float4 w0, float4 w1) {
    __nv_bfloat162* ub = (__nv_bfloat162*)&u;
    float2 f0 = __bfloat1622float2(ub[0]);
    float2 f1 = __bfloat1622float2(ub[1]);
    float2 f2 = __bfloat1622float2(ub[2]);
    float2 f3 = __bfloat1622float2(ub[3]);
    float a = tanh_hw(f0.x + p0.x) * w0.x;
    a = fmaf(tanh_hw(f0.y + p0.y), w0.y, a);
    a = fmaf(tanh_hw(f1.x + p0.z), w0.z, a);
    a = fmaf(tanh_hw(f1.y + p0.w), w0.w, a);
    a = fmaf(tanh_hw(f2.x + p1.x), w1.x, a);
    a = fmaf(tanh_hw(f2.y + p1.y), w1.y, a);
    a = fmaf(tanh_hw(f3.x + p1.z), w1.z, a);
    a = fmaf(tanh_hw(f3.y + p1.w), w1.w, a);
    return a;
}

// ---------------- grid barrier (pure spin) -------------------------------------
__device__ __forceinline__ void grid_barrier() {
    __syncthreads();
    if (threadIdx.x == 0) {
        volatile unsigned* genp = &g_bar_gen;
        unsigned gen = *genp;
        __threadfence();
        unsigned arrived = atomicAdd(&g_bar_count, 1u);
        if (arrived == NBLK - 1u) {
            *(volatile unsigned*)&g_bar_count = 0u;
            __threadfence();
            atomicExch(&g_bar_gen, gen + 1u);
        } else {
            while (*genp == gen) { }
        }
        __threadfence();
    }
    __syncthreads();
}

// ---------------- tensor-core primitives ---------------------------------------
__device__ __forceinline__ void mma16816(float* d, const unsigned* a, const unsigned* b) {
    asm volatile(
        "mma.sync.aligned.m16n8k16.row.col.f32.bf16.bf16.f32 "
        "{%0,%1,%2,%3}, {%4,%5,%6,%7}, {%8,%9}, {%0,%1,%2,%3};\n"
        : "+f"(d[0]), "+f"(d[1]), "+f"(d[2]), "+f"(d[3])
        : "r"(a[0]), "r"(a[1]), "r"(a[2]), "r"(a[3]), "r"(b[0]), "r"(b[1]));
}
__device__ __forceinline__ void ldsm4(unsigned* r, const void* p) {
    unsigned addr = (unsigned)__cvta_generic_to_shared(p);
    asm volatile("ldmatrix.sync.aligned.m8n8.x4.shared.b16 {%0,%1,%2,%3}, [%4];\n"
                 : "=r"(r[0]), "=r"(r[1]), "=r"(r[2]), "=r"(r[3]) : "r"(addr));
}

struct SmemTC {
    __nv_bfloat16 Ah[2][128][PITCH];
    __nv_bfloat16 Al[2][128][PITCH];
    __nv_bfloat16 Bh[2][64][PITCH];
    __nv_bfloat16 Bl[2][64][PITCH];
};   // 36864 B

// C[128 m][64 n] = sum_k A[m,k]*B[n,k], split-bf16, fp32 accumulate.
// AL: include A_lo*B_hi term. BL: include A_hi*B_lo term. (AL&&BL = 3 MMAs)
template<bool BF16OUT, bool AL = true, bool BL = true>
__device__ void gemm_tc(const __nv_bfloat16* __restrict__ Ah,
                        const __nv_bfloat16* __restrict__ Al, long lda,
                        const __nv_bfloat16* __restrict__ Bh,
                        const __nv_bfloat16* __restrict__ Bl, long ldb,
                        int kcount, void* __restrict__ Cv, int ldc, SmemTC* sm)
{
    const int tid = threadIdx.x;
    const int lane = tid & 31, wp = tid >> 5;
    const int m0 = (wp & 3) * 32, n0 = (wp >> 2) * 32;

    const int ar = tid >> 1, ac = (tid & 1) * 8;
    const int br = (tid & 127) >> 1, bc2 = (tid & 1) * 8;
    const bool blo = tid >= 128;
    const __nv_bfloat16* Bsrc = blo ? Bl : Bh;

    uint4 pah = *(const uint4*)(Ah + (long)ar * lda + ac);
    uint4 pal;
    if (AL) pal = *(const uint4*)(Al + (long)ar * lda + ac);
    uint4 pb;
    if (BL || !blo) pb = *(const uint4*)(Bsrc + (long)br * ldb + bc2);

    float acc[2][4][4];
#pragma unroll
    for (int i = 0; i < 2; i++)
#pragma unroll
        for (int j = 0; j < 4; j++)
#pragma unroll
            for (int k = 0; k < 4; k++) acc[i][j][k] = 0.0f;

    const int arow = lane & 15;
    const int acol = (lane & 16) ? 8 : 0;
    const int brow = (lane & 7) + ((lane & 16) ? 8 : 0);
    const int bcol = (lane & 8) ? 8 : 0;

    int buf = 0;
    for (int kt = 0; kt < kcount; kt += 16) {
        *(uint4*)&sm->Ah[buf][ar][ac] = pah;
        if (AL) *(uint4*)&sm->Al[buf][ar][ac] = pal;
        if (!blo) *(uint4*)&sm->Bh[buf][br][bc2] = pb;
        else if (BL) *(uint4*)&sm->Bl[buf][br][bc2] = pb;
        __syncthreads();
        if (kt + 16 < kcount) {
            pah = *(const uint4*)(Ah + (long)ar * lda + kt + 16 + ac);
            if (AL) pal = *(const uint4*)(Al + (long)ar * lda + kt + 16 + ac);
            if (BL || !blo) pb = *(const uint4*)(Bsrc + (long)br * ldb + kt + 16 + bc2);
        }
        unsigned afh[2][4], afl[2][4];
#pragma unroll
        for (int mt = 0; mt < 2; mt++) {
            ldsm4(afh[mt], &sm->Ah[buf][m0 + mt * 16 + arow][acol]);
            if (AL) ldsm4(afl[mt], &sm->Al[buf][m0 + mt * 16 + arow][acol]);
        }
        unsigned bfh[4][2], bfl[4][2];
#pragma unroll
        for (int hf = 0; hf < 2; hf++) {
            unsigned r[4];
            ldsm4(r, &sm->Bh[buf][n0 + hf * 16 + brow][bcol]);
            bfh[2*hf][0] = r[0]; bfh[2*hf][1] = r[1];
            bfh[2*hf+1][0] = r[2]; bfh[2*hf+1][1] = r[3];
            if (BL) {
                ldsm4(r, &sm->Bl[buf][n0 + hf * 16 + brow][bcol]);
                bfl[2*hf][0] = r[0]; bfl[2*hf][1] = r[1];
                bfl[2*hf+1][0] = r[2]; bfl[2*hf+1][1] = r[3];
            }
        }
#pragma unroll
        for (int mt = 0; mt < 2; mt++)
#pragma unroll
            for (int nt = 0; nt < 4; nt++) {
                mma16816(acc[mt][nt], afh[mt], bfh[nt]);
                if (BL) mma16816(acc[mt][nt], afh[mt], bfl[nt]);
                if (AL) mma16816(acc[mt][nt], afl[mt], bfh[nt]);
            }
        buf ^= 1;
    }
    const int gr = lane >> 2, gc = (lane & 3) * 2;
#pragma unroll
    for (int mt = 0; mt < 2; mt++)
#pragma unroll
        for (int nt = 0; nt < 4; nt++) {
            long base = (long)(m0 + mt * 16 + gr) * ldc + n0 + nt * 8 + gc;
            if (BF16OUT) {
                __nv_bfloat16* C = (__nv_bfloat16*)Cv;
                *(__nv_bfloat162*)&C[base] =
                    __floats2bfloat162_rn(acc[mt][nt][0], acc[mt][nt][1]);
                *(__nv_bfloat162*)&C[base + 8 * ldc] =
                    __floats2bfloat162_rn(acc[mt][nt][2], acc[mt][nt][3]);
            } else {
                float* C = (float*)Cv;
                *(float2*)&C[base]           = make_float2(acc[mt][nt][0], acc[mt][nt][1]);
                *(float2*)&C[base + 8 * ldc] = make_float2(acc[mt][nt][2], acc[mt][nt][3]);
            }
        }
}

// ---------------- prep kernels --------------------------------------------------
__device__ void conv_seg(const float* __restrict__ x, __nv_bfloat16* __restrict__ hi,
                         __nv_bfloat16* __restrict__ lo, long n, long t0, long stride)
{
    for (long i = t0; i < n; i += stride) {
        float v = x[i];
        __nv_bfloat16 hb = __float2bfloat16(v);
        hi[i] = hb;
        lo[i] = __float2bfloat16(v - __bfloat162float(hb));
    }
}

__global__ void conv_all(const float* w_h_a, const float* w_init_s, const float* w_s_a,
                         const float* gru_w_hh, const float* gru_w_ih,
                         const float* rnn_w_ih, const float* rnn_w_hh, const float* h)
{
    long t0 = (long)blockIdx.x * blockDim.x + threadIdx.x;
    long st = (long)gridDim.x * blockDim.x;
    conv_seg(w_h_a,    g_wha_h, g_wha_l, (long)1024 * 1024, t0, st);
    conv_seg(w_init_s, g_wis_h, g_wis_l, (long)1024 * 1024, t0, st);
    conv_seg(w_s_a,    g_wsa_h, g_wsa_l, (long)1024 * 1024, t0, st);
    conv_seg(gru_w_hh, g_gwh_h, g_gwh_l, (long)3072 * 1024, t0, st);
    conv_seg(gru_w_ih, g_gwi_h, g_gwi_l, (long)3072 * 2048, t0, st);
    conv_seg(rnn_w_ih, g_rwi_h, g_rwi_l, (long)1024 * 2048, t0, st);
    conv_seg(rnn_w_hh, g_rwh_h, g_rwh_l, (long)1024 * 1024, t0, st);
    for (long i = t0; i < (long)Bb * Tt * Dd; i += st) {
        float v = h[i];
        __nv_bfloat16 hb = __float2bfloat16(v);
        g_h_h[i] = hb;
        g_h_l[i] = __float2bfloat16(v - __bfloat162float(hb));
        g_hf16[i] = __float2half(v);
    }
}

// wh (4096 blocks, 1-MMA hi*hi) + s0 partials (64 blocks, 3-MMA) in one launch
__global__ void __launch_bounds__(256, 2) prep_gemm_kernel()
{
    __shared__ __align__(16) SmemTC sm;
    int blk = blockIdx.x;
    if (blk < 4096) {
        int nt = blk & 15, mb = blk >> 4;
        gemm_tc<true, false, false>(
            g_h_h + (long)mb * 128 * 1024, g_h_l + (long)mb * 128 * 1024, 1024,
            g_wha_h + (long)nt * 64 * 1024, g_wha_l + (long)nt * 64 * 1024, 1024,
            1024, g_whb + (long)mb * 128 * 1024 + nt * 64, 1024, &sm);
    } else {
        int i = blk - 4096, nt = i & 15, z = i >> 4;   // 4 k-splits of 256
        gemm_tc<false>(g_h_h + z * 256, g_h_l + z * 256, (long)Tt * Dd,
                       g_wis_h + (long)nt * 64 * 1024 + z * 256,
                       g_wis_l + (long)nt * 64 * 1024 + z * 256, 1024,
                       256, g_part_proj + z * (Bb * Hh) + nt * 64, 1024, &sm);
    }
}

__global__ void init_state_kernel(const float* __restrict__ bias)
{
    int idx = blockIdx.x * 256 + threadIdx.x;   // < 128*1024
    int hh = idx & 1023;
    float v = bias[hh];
#pragma unroll
    for (int q = 0; q < 4; q++) v += g_part_proj[q * (Bb * Hh) + idx];
    float s = tanh_mufu(v);
    g_s[idx] = s;
    split_w(s, g_s_h, g_s_l, idx);
    g_y_h[idx] = __float2bfloat16(0.0f);
    g_y_l[idx] = __float2bfloat16(0.0f);
    if (idx < Bb) g_bsync[idx] = 0;
    if (idx == 0) { g_bar_count = 0; g_bar_gen = 0; }
}

// ---------------- zeta: out = softmax(tanh(pre)); updates y splits --------------
__device__ void zeta_phase(int b, int step, int par, const float* rnn_b_ih,
                           const float* rnn_b_hh, float* out, float* red, float* s_bc)
{
    const int tid = threadIdx.x;
    const int w = tid >> 5, l = tid & 31;
    const float* pp = g_part_pre + (long)par * 8 * BV;
    float4 acc = ((const float4*)rnn_b_ih)[tid];
    float4 b2  = ((const float4*)rnn_b_hh)[tid];
    acc.x += b2.x; acc.y += b2.y; acc.z += b2.z; acc.w += b2.w;
#pragma unroll
    for (int q = 0; q < 8; q++) {
        float4 p = ((const float4*)(pp + (long)q * BV + b * Vv))[tid];
        acc.x += p.x; acc.y += p.y; acc.z += p.z; acc.w += p.w;
    }
    float t0 = tanh_mufu(acc.x), t1 = tanh_mufu(acc.y);
    float t2 = tanh_mufu(acc.z), t3 = tanh_mufu(acc.w);
    float m = fmaxf(fmaxf(t0, t1), fmaxf(t2, t3));
    m = warp_max(m);
    if (l == 0) red[w] = m;
    __syncthreads();
    if (tid == 0) {
        float mm = red[0];
#pragma unroll
        for (int i = 1; i < 8; i++) mm = fmaxf(mm, red[i]);
        *s_bc = mm;
    }
    __syncthreads();
    float mx = *s_bc;
    float e0 = exp_mufu(t0 - mx), e1 = exp_mufu(t1 - mx);
    float e2 = exp_mufu(t2 - mx), e3 = exp_mufu(t3 - mx);
    float s = warp_sum(e0 + e1 + e2 + e3);
    if (l == 0) red[w] = s;
    __syncthreads();
    if (tid == 0) {
        float ss = 0.0f;
#pragma unroll
        for (int i = 0; i < 8; i++) ss += red[i];
        *s_bc = rcp_approx(ss);
    }
    __syncthreads();
    float inv = *s_bc;
    float y0 = e0 * inv, y1 = e1 * inv, y2 = e2 * inv, y3 = e3 * inv;
    long base = (long)b * 1024 + tid * 4;
    split_w(y0, g_y_h, g_y_l, base + 0);
    split_w(y1, g_y_h, g_y_l, base + 1);
    split_w(y2, g_y_h, g_y_l, base + 2);
    split_w(y3, g_y_h, g_y_l, base + 3);
    ((float4*)(out + ((long)b * Ss + step) * Vv))[tid] = make_float4(y0, y1, y2, y3);
    __syncthreads();
}

// ---------------- the persistent kernel -----------------------------------------
__global__ void __launch_bounds__(256, 2)
persist_kernel(const float* __restrict__ b_s_a, const float* __restrict__ w_a,
               const float* __restrict__ gru_b_ih, const float* __restrict__ gru_b_hh,
               const float* __restrict__ rnn_b_ih, const float* __restrict__ rnn_b_hh,
               float* __restrict__ out)
{
    __shared__ __align__(16) unsigned char sraw[sizeof(SmemTC)];
    __shared__ float s_bc;
    SmemTC* sm = (SmemTC*)sraw;
    float* p_sh = (float*)sraw;        // 1024 floats (proj; reused for ctx partials)
    float* w_sh = p_sh + 1024;         // 1024 (w_a)
    float* sc   = w_sh + 1024;         // 256 (softmax a)
    float* red  = sc + 256;            // 8

    const int blk = blockIdx.x;
    const int tid = threadIdx.x;
    const int w = tid >> 5, l = tid & 31;

    // ==== Phi0: proj for step 0 (blocks 0-63) + gh for step 0 (blocks 64-159)
    if (blk < 64) {
        int nt = blk >> 2, z = blk & 3;
        gemm_tc<false>(g_s_h + z * 256, g_s_l + z * 256, 1024,
                       g_wsa_h + (long)nt * 64 * 1024 + z * 256,
                       g_wsa_l + (long)nt * 64 * 1024 + z * 256, 1024,
                       256, g_part_proj + z * (Bb * Hh) + nt * 64, Hh, sm);
    } else if (blk < 160) {   // gh_0 = s0 @ gru_w_hh^T : 48nt x 2z, K=512
        int i = blk - 64, nt = i >> 1, z = i & 1;
        gemm_tc<false>(g_s_h + z * 512, g_s_l + z * 512, 1024,
                       g_gwh_h + (long)nt * 64 * 1024 + z * 512,
                       g_gwh_l + (long)nt * 64 * 1024 + z * 512, 1024,
                       512, g_part_gh + (long)z * (Bb * H3) + nt * 64, H3, sm);
    }
    grid_barrier();

    for (int step = 0; step < Ss; step++) {
        const int par = step & 1;

        // ==== Phi1: beta2 (blocks 0-255: pair (b, half)) || zeta_prev (256-295)
        if (blk < 256) {
            const int b = blk >> 1, half = blk & 1;
            {
                float4 acc = ((const float4*)b_s_a)[tid];
#pragma unroll
                for (int z = 0; z < 4; z++) {
                    float4 v = ((const float4*)(g_part_proj + z * (Bb * Hh) + b * Hh))[tid];
                    acc.x += v.x; acc.y += v.y; acc.z += v.z; acc.w += v.w;
                }
                ((float4*)p_sh)[tid] = acc;
                ((float4*)w_sh)[tid] = ((const float4*)w_a)[tid];
            }
            __syncthreads();
            // scores: wh loads DEFAULT-cached (wh is L2-resident, 67MB < L2);
            // 8-deep load batching; all reductions deferred.
            {
                const uint4* whb4 = (const uint4*)(g_whb + (long)b * Tt * Hh);
                int t0 = half * 128 + w * 16;
                float a[16];
#pragma unroll
                for (int q = 0; q < 16; q++) a[q] = 0.0f;
#pragma unroll
                for (int tt8 = 0; tt8 < 16; tt8 += 8) {
                    int t = t0 + tt8;
#pragma unroll
                    for (int jj = 0; jj < 4; jj++) {
                        int fi = jj * 32 + l;
                        uint4 u[8];
#pragma unroll
                        for (int q = 0; q < 8; q++)
                            u[q] = __ldg(&whb4[(long)(t + q) * 128 + fi]);
                        float4 p0 = ((const float4*)p_sh)[fi * 2];
                        float4 p1 = ((const float4*)p_sh)[fi * 2 + 1];
                        float4 w0 = ((const float4*)w_sh)[fi * 2];
                        float4 w1 = ((const float4*)w_sh)[fi * 2 + 1];
#pragma unroll
                        for (int q = 0; q < 8; q++)
                            a[tt8 + q] += score8(u[q], p0, p1, w0, w1);
                    }
                }
#pragma unroll
                for (int q = 0; q < 16; q++) a[q] = warp_sum(a[q]);
                if (l == 0) {
#pragma unroll
                    for (int q = 0; q < 16; q++)
                        g_scores[b * Tt + t0 + q] = a[q];
                }
            }
            // per-b sync between the two halves (monotonic counter)
            __threadfence();
            __syncthreads();
            if (tid == 0) {
                atomicAdd(&g_bsync[b], 1u);
                unsigned target = 2u * (unsigned)(step + 1);
                while (*(volatile unsigned*)&g_bsync[b] < target) { }
                __threadfence();
            }
            __syncthreads();
            // softmax over all 256 scores (both blocks of the pair compute it)
            {
                float v = g_scores[b * Tt + tid];
                float m = warp_max(v);
                if (l == 0) red[w] = m;
                __syncthreads();
                if (tid == 0) {
                    float mm = red[0];
#pragma unroll
                    for (int i = 1; i < 8; i++) mm = fmaxf(mm, red[i]);
                    s_bc = mm;
                }
                __syncthreads();
                float e = exp_mufu(v - s_bc);
                float s = warp_sum(e);
                if (l == 0) red[w] = s;
                __syncthreads();
                if (tid == 0) {
                    float ss = 0.0f;
#pragma unroll
                    for (int i = 0; i < 8; i++) ss += red[i];
                    s_bc = rcp_approx(ss);
                }
                __syncthreads();
                sc[tid] = e * s_bc;
            }
            __syncthreads();
            // ctx: h-fp16 stays STREAMING (evict-first) so it can't evict wh
            {
                const int sub = tid >> 6, pos = tid & 63;
                const uint4* hp16 = (const uint4*)(g_hf16 + (long)b * Tt * Dd);
                float cr[8];
#pragma unroll
                for (int q = 0; q < 8; q++) cr[q] = 0.0f;
                for (int i = 0; i < 64; i += 8) {     // t = sub + 4*(i+j)
                    uint4 u[8];
                    float av[8];
#pragma unroll
                    for (int j = 0; j < 8; j++) {
                        int t = sub + 4 * (i + j);
                        u[j] = ldg_ef(&hp16[(long)t * 128 + half * 64 + pos]);
                        av[j] = sc[t];
                    }
#pragma unroll
                    for (int j = 0; j < 8; j++) {
                        __half2* hh2 = (__half2*)&u[j];
                        float a = av[j];
#pragma unroll
                        for (int q = 0; q < 4; q++) {
                            float2 f = __half22float2(hh2[q]);
                            cr[2*q]   = fmaf(a, f.x, cr[2*q]);
                            cr[2*q+1] = fmaf(a, f.y, cr[2*q+1]);
                        }
                    }
                }
                __syncthreads();      // p_sh/w_sh free now (scores done)
                float* part = p_sh;   // [4][512] = 2048 floats
#pragma unroll
                for (int q = 0; q < 8; q++) part[sub * 512 + pos * 8 + q] = cr[q];
                __syncthreads();
                long cb = (long)b * 1024 + half * 512;
#pragma unroll
                for (int r2 = 0; r2 < 2; r2++) {
                    int d = tid * 2 + r2;
                    float v = part[d] + part[512 + d] + part[1024 + d] + part[1536 + d];
                    split_w(v, g_c_h, g_c_l, cb + d);
                }
            }
        } else if (step > 0) {   // zeta for step-1: blocks 256-295 grid-stride
            for (int bb = blk - 256; bb < Bb; bb += 40)
                zeta_phase(bb, step - 1, par ^ 1, rnn_b_ih, rnn_b_hh, out, red, &s_bc);
        }
        grid_barrier();

        // ==== Phi2: gi_y(0-95) || gi_c(96-191) || pre_ih_c(192-223) || pre_hh(224-255)
        if (blk < 96) {
            int nt = blk >> 1, z = blk & 1;
            gemm_tc<false>(g_y_h + z * 512, g_y_l + z * 512, 1024,
                           g_gwi_h + (long)nt * 64 * 2048 + 1024 + z * 512,
                           g_gwi_l + (long)nt * 64 * 2048 + 1024 + z * 512, 2048,
                           512, g_part_gi + (long)z * (Bb * H3) + nt * 64, H3, sm);
        } else if (blk < 192) {
            int i = blk - 96, nt = i >> 1, z = i & 1;
            gemm_tc<false>(g_c_h + z * 512, g_c_l + z * 512, 1024,
                           g_gwi_h + (long)nt * 64 * 2048 + z * 512,
                           g_gwi_l + (long)nt * 64 * 2048 + z * 512, 2048,
                           512, g_part_gi + (long)(2 + z) * (Bb * H3) + nt * 64, H3, sm);
        } else if (blk < 224) {
            int i = blk - 192, nt = i >> 1, z = i & 1;
            gemm_tc<false>(g_c_h + z * 512, g_c_l + z * 512, 1024,
                           g_rwi_h + (long)nt * 64 * 2048 + z * 512,
                           g_rwi_l + (long)nt * 64 * 2048 + z * 512, 2048,
                           512, g_part_pre + ((long)par * 8 + z) * BV + nt * 64, Vv, sm);
        } else if (blk < 256) {
            int i = blk - 224, nt = i >> 1, z = i & 1;
            gemm_tc<false>(g_y_h + z * 512, g_y_l + z * 512, 1024,
                           g_rwh_h + (long)nt * 64 * 1024 + z * 512,
                           g_rwh_l + (long)nt * 64 * 1024 + z * 512, 1024,
                           512, g_part_pre + ((long)par * 8 + 6 + z) * BV + nt * 64, Vv, sm);
        }
        grid_barrier();

        // ==== Phi3: GRU elementwise
        for (int idx = blk * 256 + tid; idx < Bb * Hh; idx += NBLK * 256) {
            int b = idx >> 10, hh = idx & 1023;
            float gir = gru_b_ih[hh], giz = gru_b_ih[1024 + hh], gin = gru_b_ih[2048 + hh];
#pragma unroll
            for (int q = 0; q < 4; q++) {
                const float* p = g_part_gi + (long)(q * Bb + b) * H3 + hh;
                gir += p[0]; giz += p[1024]; gin += p[2048];
            }
            float ghr = gru_b_hh[hh], ghz = gru_b_hh[1024 + hh], ghn = gru_b_hh[2048 + hh];
#pragma unroll
            for (int q = 0; q < 2; q++) {
                const float* p = g_part_gh + (long)(q * Bb + b) * H3 + hh;
                ghr += p[0]; ghz += p[1024]; ghn += p[2048];
            }
            float r = sigmoid_mufu(gir + ghr);
            float z = sigmoid_mufu(giz + ghz);
            float n = tanh_mufu(fmaf(r, ghn, gin));
            float sv = g_s[idx];
            float sn = fmaf(z, sv - n, n);
            g_s[idx] = sn;
            split_w(sn, g_s_h, g_s_l, idx);
        }
        grid_barrier();

        // ==== Phi4: pre_ih_s(0-63, K=256) || proj_next(64-127, K=256) || gh_next(128-223, K=512)
        if (blk < 64) {
            int nt = blk >> 2, z = blk & 3;
            gemm_tc<false>(g_s_h + z * 256, g_s_l + z * 256, 1024,
                           g_rwi_h + (long)nt * 64 * 2048 + 1024 + z * 256,
                           g_rwi_l + (long)nt * 64 * 2048 + 1024 + z * 256, 2048,
                           256, g_part_pre + ((long)par * 8 + 2 + z) * BV + nt * 64, Vv, sm);
        } else if (blk < 128) {
            int i = blk - 64, nt = i >> 2, z = i & 3;
            gemm_tc<false>(g_s_h + z * 256, g_s_l + z * 256, 1024,
                           g_wsa_h + (long)nt * 64 * 1024 + z * 256,
                           g_wsa_l + (long)nt * 64 * 1024 + z * 256, 1024,
                           256, g_part_proj + z * (Bb * Hh) + nt * 64, Hh, sm);
        } else if (blk < 224) {
            int i = blk - 128, nt = i >> 1, z = i & 1;
            gemm_tc<false>(g_s_h + z * 512, g_s_l + z * 512, 1024,
                           g_gwh_h + (long)nt * 64 * 1024 + z * 512,
                           g_gwh_l + (long)nt * 64 * 1024 + z * 512, 1024,
                           512, g_part_gh + (long)z * (Bb * H3) + nt * 64, H3, sm);
        }
        grid_barrier();
    }
    // tail: zeta for the final step
    if (blk < 128) {
        zeta_phase(blk, Ss - 1, (Ss - 1) & 1, rnn_b_ih, rnn_b_hh, out, red, &s_bc);
    }
}

// ---------------- launcher -------------------------------------------------------
extern "C" void kernel_launch(void* const* d_in, const int* in_sizes, int n_in,
                              void* d_out, int out_size)
{
    const float* h        = (const float*)d_in[0];
    const float* w_h_a    = (const float*)d_in[1];
    const float* w_s_a    = (const float*)d_in[2];
    const float* b_s_a    = (const float*)d_in[3];
    const float* w_a      = (const float*)d_in[4];
    const float* w_init_s = (const float*)d_in[5];
    const float* b_init_s = (const float*)d_in[6];
    const float* gru_w_ih = (const float*)d_in[7];
    const float* gru_w_hh = (const float*)d_in[8];
    const float* gru_b_ih = (const float*)d_in[9];
    const float* gru_b_hh = (const float*)d_in[10];
    const float* rnn_w_ih = (const float*)d_in[11];
    const float* rnn_w_hh = (const float*)d_in[12];
    const float* rnn_b_ih = (const float*)d_in[13];
    const float* rnn_b_hh = (const float*)d_in[14];
    float* out = (float*)d_out;

    conv_all<<<2048, 256>>>(w_h_a, w_init_s, w_s_a, gru_w_hh, gru_w_ih,
                            rnn_w_ih, rnn_w_hh, h);
    prep_gemm_kernel<<<4160, 256>>>();
    init_state_kernel<<<512, 256>>>(b_init_s);
    persist_kernel<<<NBLK, 256>>>(b_s_a, w_a, gru_b_ih, gru_b_hh,
                                  rnn_b_ih, rnn_b_hh, out);
    (void)in_sizes; (void)n_in; (void)out_size;
}

// round 15
// speedup vs baseline: 1.0481x; 1.0481x over previous
#include <cuda_runtime.h>
#include <cuda_bf16.h>
#include <cuda_fp16.h>

#define Bb 128
#define Tt 256
#define Dd 1024
#define Hh 1024
#define Vv 1024
#define Ss 128
#define H3 3072
#define NBLK 296
#define PITCH 24
#define BV (Bb * Vv)

// ---------------- scratch (device globals; no cudaMalloc allowed) -----------
__device__ __align__(16) __nv_bfloat16 g_whb[(long)Bb * Tt * Hh];  // 67 MB bf16
__device__ __align__(16) __half g_hf16[(long)Bb * Tt * Dd];        // 67 MB fp16
__device__ __align__(16) float g_part_proj[4 * Bb * Hh];
__device__ __align__(16) float g_part_gi[4 * Bb * H3];   // 0,1=gi_y  2,3=gi_c
__device__ __align__(16) float g_part_gh[2 * Bb * H3];
__device__ __align__(16) float g_part_pre[2 * 8 * BV];   // [par][slot]: 0,1 ihc; 2-5 ihs; 6,7 hh
__device__ __align__(16) float g_s[Bb * Hh];
__device__ __align__(16) float g_scores[Bb * Tt];
__device__ unsigned g_bsync[Bb];

// split-bf16 mirrors: value = hi + lo
__device__ __align__(16) __nv_bfloat16 g_s_h[Bb * Hh], g_s_l[Bb * Hh];
__device__ __align__(16) __nv_bfloat16 g_c_h[Bb * Hh], g_c_l[Bb * Hh];
__device__ __align__(16) __nv_bfloat16 g_y_h[Bb * Hh], g_y_l[Bb * Hh];
// weights (split)
__device__ __align__(16) __nv_bfloat16 g_wsa_h[1024 * 1024], g_wsa_l[1024 * 1024];
__device__ __align__(16) __nv_bfloat16 g_gwh_h[3072 * 1024], g_gwh_l[3072 * 1024];
__device__ __align__(16) __nv_bfloat16 g_gwi_h[(long)3072 * 2048], g_gwi_l[(long)3072 * 2048];
__device__ __align__(16) __nv_bfloat16 g_rwi_h[(long)1024 * 2048], g_rwi_l[(long)1024 * 2048];
__device__ __align__(16) __nv_bfloat16 g_rwh_h[1024 * 1024], g_rwh_l[1024 * 1024];
__device__ __align__(16) __nv_bfloat16 g_wha_h[1024 * 1024], g_wha_l[1024 * 1024];
__device__ __align__(16) __nv_bfloat16 g_wis_h[1024 * 1024], g_wis_l[1024 * 1024];
__device__ __align__(16) __nv_bfloat16 g_h_h[(long)Bb * Tt * Dd], g_h_l[(long)Bb * Tt * Dd];

__device__ unsigned g_bar_count = 0;
__device__ unsigned g_bar_gen = 0;

// ---------------- math helpers -----------------------------------------------
__device__ __forceinline__ float ex2_approx(float x) {
    float r; asm("ex2.approx.ftz.f32 %0, %1;" : "=f"(r) : "f"(x)); return r;
}
__device__ __forceinline__ float rcp_approx(float x) {
    float r; asm("rcp.approx.ftz.f32 %0, %1;" : "=f"(r) : "f"(x)); return r;
}
__device__ __forceinline__ float exp_mufu(float x) {
    return ex2_approx(x * 1.4426950408889634f);
}
__device__ __forceinline__ float tanh_hw(float x) {
    float r; asm("tanh.approx.f32 %0, %1;" : "=f"(r) : "f"(x)); return r;
}
__device__ __forceinline__ float tanh_mufu(float x) {
    float ax = fabsf(x);
    float e  = ex2_approx(ax * -2.885390081777927f);
    float r  = rcp_approx(1.0f + e);
    float th = fmaf(-2.0f * e, r, 1.0f);
    return copysignf(th, x);
}
__device__ __forceinline__ float sigmoid_mufu(float x) {
    float e = ex2_approx(x * -1.4426950408889634f);
    return rcp_approx(1.0f + e);
}
__device__ __forceinline__ float warp_sum(float v) {
#pragma unroll
    for (int o = 16; o > 0; o >>= 1) v += __shfl_xor_sync(0xffffffffu, v, o);
    return v;
}
__device__ __forceinline__ float warp_max(float v) {
#pragma unroll
    for (int o = 16; o > 0; o >>= 1) v = fmaxf(v, __shfl_xor_sync(0xffffffffu, v, o));
    return v;
}
__device__ __forceinline__ void split_w(float v, __nv_bfloat16* hi, __nv_bfloat16* lo, long i) {
    __nv_bfloat16 hb = __float2bfloat16(v);
    hi[i] = hb;
    lo[i] = __float2bfloat16(v - __bfloat162float(hb));
}
// streaming load (cache-streaming / evict-first) — keeps weights L2-resident
__device__ __forceinline__ uint4 ldg_ef(const uint4* p) {
    return __ldcs(p);
}
// 8-wide tanh-dot for one wh row chunk (HW tanh)
__device__ __forceinline__ float score8(uint4 u, float4 p0, float4 p1, float4 w0, float4 w1) {
    __nv_bfloat162* ub = (__nv_bfloat162*)&u;
    float2 f0 = __bfloat1622float2(ub[0]);
    float2 f1 = __bfloat1622float2(ub[1]);
    float2 f2 = __bfloat1622float2(ub[2]);
    float2 f3 = __bfloat1622float2(ub[3]);
    float a = tanh_hw(f0.x + p0.x) * w0.x;
    a = fmaf(tanh_hw(f0.y + p0.y), w0.y, a);
    a = fmaf(tanh_hw(f1.x + p0.z), w0.z, a);
    a = fmaf(tanh_hw(f1.y + p0.w), w0.w, a);
    a = fmaf(tanh_hw(f2.x + p1.x), w1.x, a);
    a = fmaf(tanh_hw(f2.y + p1.y), w1.y, a);
    a = fmaf(tanh_hw(f3.x + p1.z), w1.z, a);
    a = fmaf(tanh_hw(f3.y + p1.w), w1.w, a);
    return a;
}

// ---------------- grid barrier (pure spin) -------------------------------------
__device__ __forceinline__ void grid_barrier() {
    __syncthreads();
    if (threadIdx.x == 0) {
        volatile unsigned* genp = &g_bar_gen;
        unsigned gen = *genp;
        __threadfence();
        unsigned arrived = atomicAdd(&g_bar_count, 1u);
        if (arrived == NBLK - 1u) {
            *(volatile unsigned*)&g_bar_count = 0u;
            __threadfence();
            atomicExch(&g_bar_gen, gen + 1u);
        } else {
            while (*genp == gen) { }
        }
        __threadfence();
    }
    __syncthreads();
}

// ---------------- tensor-core primitives ---------------------------------------
__device__ __forceinline__ void mma16816(float* d, const unsigned* a, const unsigned* b) {
    asm volatile(
        "mma.sync.aligned.m16n8k16.row.col.f32.bf16.bf16.f32 "
        "{%0,%1,%2,%3}, {%4,%5,%6,%7}, {%8,%9}, {%0,%1,%2,%3};\n"
        : "+f"(d[0]), "+f"(d[1]), "+f"(d[2]), "+f"(d[3])
        : "r"(a[0]), "r"(a[1]), "r"(a[2]), "r"(a[3]), "r"(b[0]), "r"(b[1]));
}
__device__ __forceinline__ void ldsm4(unsigned* r, const void* p) {
    unsigned addr = (unsigned)__cvta_generic_to_shared(p);
    asm volatile("ldmatrix.sync.aligned.m8n8.x4.shared.b16 {%0,%1,%2,%3}, [%4];\n"
                 : "=r"(r[0]), "=r"(r[1]), "=r"(r[2]), "=r"(r[3]) : "r"(addr));
}

struct SmemTC {
    __nv_bfloat16 Ah[2][128][PITCH];
    __nv_bfloat16 Al[2][128][PITCH];
    __nv_bfloat16 Bh[2][64][PITCH];
    __nv_bfloat16 Bl[2][64][PITCH];
};   // 36864 B

// C[128 m][64 n] = sum_k A[m,k]*B[n,k], split-bf16, fp32 accumulate.
// AL: include A_lo*B_hi term. BL: include A_hi*B_lo term. (AL&&BL = 3 MMAs)
template<bool BF16OUT, bool AL = true, bool BL = true>
__device__ void gemm_tc(const __nv_bfloat16* __restrict__ Ah,
                        const __nv_bfloat16* __restrict__ Al, long lda,
                        const __nv_bfloat16* __restrict__ Bh,
                        const __nv_bfloat16* __restrict__ Bl, long ldb,
                        int kcount, void* __restrict__ Cv, int ldc, SmemTC* sm)
{
    const int tid = threadIdx.x;
    const int lane = tid & 31, wp = tid >> 5;
    const int m0 = (wp & 3) * 32, n0 = (wp >> 2) * 32;

    const int ar = tid >> 1, ac = (tid & 1) * 8;
    const int br = (tid & 127) >> 1, bc2 = (tid & 1) * 8;
    const bool blo = tid >= 128;
    const __nv_bfloat16* Bsrc = blo ? Bl : Bh;

    uint4 pah = *(const uint4*)(Ah + (long)ar * lda + ac);
    uint4 pal;
    if (AL) pal = *(const uint4*)(Al + (long)ar * lda + ac);
    uint4 pb;
    if (BL || !blo) pb = *(const uint4*)(Bsrc + (long)br * ldb + bc2);

    float acc[2][4][4];
#pragma unroll
    for (int i = 0; i < 2; i++)
#pragma unroll
        for (int j = 0; j < 4; j++)
#pragma unroll
            for (int k = 0; k < 4; k++) acc[i][j][k] = 0.0f;

    const int arow = lane & 15;
    const int acol = (lane & 16) ? 8 : 0;
    const int brow = (lane & 7) + ((lane & 16) ? 8 : 0);
    const int bcol = (lane & 8) ? 8 : 0;

    int buf = 0;
    for (int kt = 0; kt < kcount; kt += 16) {
        *(uint4*)&sm->Ah[buf][ar][ac] = pah;
        if (AL) *(uint4*)&sm->Al[buf][ar][ac] = pal;
        if (!blo) *(uint4*)&sm->Bh[buf][br][bc2] = pb;
        else if (BL) *(uint4*)&sm->Bl[buf][br][bc2] = pb;
        __syncthreads();
        if (kt + 16 < kcount) {
            pah = *(const uint4*)(Ah + (long)ar * lda + kt + 16 + ac);
            if (AL) pal = *(const uint4*)(Al + (long)ar * lda + kt + 16 + ac);
            if (BL || !blo) pb = *(const uint4*)(Bsrc + (long)br * ldb + kt + 16 + bc2);
        }
        unsigned afh[2][4], afl[2][4];
#pragma unroll
        for (int mt = 0; mt < 2; mt++) {
            ldsm4(afh[mt], &sm->Ah[buf][m0 + mt * 16 + arow][acol]);
            if (AL) ldsm4(afl[mt], &sm->Al[buf][m0 + mt * 16 + arow][acol]);
        }
        unsigned bfh[4][2], bfl[4][2];
#pragma unroll
        for (int hf = 0; hf < 2; hf++) {
            unsigned r[4];
            ldsm4(r, &sm->Bh[buf][n0 + hf * 16 + brow][bcol]);
            bfh[2*hf][0] = r[0]; bfh[2*hf][1] = r[1];
            bfh[2*hf+1][0] = r[2]; bfh[2*hf+1][1] = r[3];
            if (BL) {
                ldsm4(r, &sm->Bl[buf][n0 + hf * 16 + brow][bcol]);
                bfl[2*hf][0] = r[0]; bfl[2*hf][1] = r[1];
                bfl[2*hf+1][0] = r[2]; bfl[2*hf+1][1] = r[3];
            }
        }
#pragma unroll
        for (int mt = 0; mt < 2; mt++)
#pragma unroll
            for (int nt = 0; nt < 4; nt++) {
                mma16816(acc[mt][nt], afh[mt], bfh[nt]);
                if (BL) mma16816(acc[mt][nt], afh[mt], bfl[nt]);
                if (AL) mma16816(acc[mt][nt], afl[mt], bfh[nt]);
            }
        buf ^= 1;
    }
    const int gr = lane >> 2, gc = (lane & 3) * 2;
#pragma unroll
    for (int mt = 0; mt < 2; mt++)
#pragma unroll
        for (int nt = 0; nt < 4; nt++) {
            long base = (long)(m0 + mt * 16 + gr) * ldc + n0 + nt * 8 + gc;
            if (BF16OUT) {
                __nv_bfloat16* C = (__nv_bfloat16*)Cv;
                *(__nv_bfloat162*)&C[base] =
                    __floats2bfloat162_rn(acc[mt][nt][0], acc[mt][nt][1]);
                *(__nv_bfloat162*)&C[base + 8 * ldc] =
                    __floats2bfloat162_rn(acc[mt][nt][2], acc[mt][nt][3]);
            } else {
                float* C = (float*)Cv;
                *(float2*)&C[base]           = make_float2(acc[mt][nt][0], acc[mt][nt][1]);
                *(float2*)&C[base + 8 * ldc] = make_float2(acc[mt][nt][2], acc[mt][nt][3]);
            }
        }
}

// ---------------- prep kernels --------------------------------------------------
__device__ void conv_seg(const float* __restrict__ x, __nv_bfloat16* __restrict__ hi,
                         __nv_bfloat16* __restrict__ lo, long n, long t0, long stride)
{
    for (long i = t0; i < n; i += stride) {
        float v = x[i];
        __nv_bfloat16 hb = __float2bfloat16(v);
        hi[i] = hb;
        lo[i] = __float2bfloat16(v - __bfloat162float(hb));
    }
}

__global__ void conv_all(const float* w_h_a, const float* w_init_s, const float* w_s_a,
                         const float* gru_w_hh, const float* gru_w_ih,
                         const float* rnn_w_ih, const float* rnn_w_hh, const float* h)
{
    long t0 = (long)blockIdx.x * blockDim.x + threadIdx.x;
    long st = (long)gridDim.x * blockDim.x;
    conv_seg(w_h_a,    g_wha_h, g_wha_l, (long)1024 * 1024, t0, st);
    conv_seg(w_init_s, g_wis_h, g_wis_l, (long)1024 * 1024, t0, st);
    conv_seg(w_s_a,    g_wsa_h, g_wsa_l, (long)1024 * 1024, t0, st);
    conv_seg(gru_w_hh, g_gwh_h, g_gwh_l, (long)3072 * 1024, t0, st);
    conv_seg(gru_w_ih, g_gwi_h, g_gwi_l, (long)3072 * 2048, t0, st);
    conv_seg(rnn_w_ih, g_rwi_h, g_rwi_l, (long)1024 * 2048, t0, st);
    conv_seg(rnn_w_hh, g_rwh_h, g_rwh_l, (long)1024 * 1024, t0, st);
    for (long i = t0; i < (long)Bb * Tt * Dd; i += st) {
        float v = h[i];
        __nv_bfloat16 hb = __float2bfloat16(v);
        g_h_h[i] = hb;
        g_h_l[i] = __float2bfloat16(v - __bfloat162float(hb));
        g_hf16[i] = __float2half(v);
    }
}

// wh (4096 blocks, 1-MMA hi*hi) + s0 partials (64 blocks, 3-MMA) in one launch
__global__ void __launch_bounds__(256, 2) prep_gemm_kernel()
{
    __shared__ __align__(16) SmemTC sm;
    int blk = blockIdx.x;
    if (blk < 4096) {
        int nt = blk & 15, mb = blk >> 4;
        gemm_tc<true, false, false>(
            g_h_h + (long)mb * 128 * 1024, g_h_l + (long)mb * 128 * 1024, 1024,
            g_wha_h + (long)nt * 64 * 1024, g_wha_l + (long)nt * 64 * 1024, 1024,
            1024, g_whb + (long)mb * 128 * 1024 + nt * 64, 1024, &sm);
    } else {
        int i = blk - 4096, nt = i & 15, z = i >> 4;   // 4 k-splits of 256
        gemm_tc<false>(g_h_h + z * 256, g_h_l + z * 256, (long)Tt * Dd,
                       g_wis_h + (long)nt * 64 * 1024 + z * 256,
                       g_wis_l + (long)nt * 64 * 1024 + z * 256, 1024,
                       256, g_part_proj + z * (Bb * Hh) + nt * 64, 1024, &sm);
    }
}

__global__ void init_state_kernel(const float* __restrict__ bias)
{
    int idx = blockIdx.x * 256 + threadIdx.x;   // < 128*1024
    int hh = idx & 1023;
    float v = bias[hh];
#pragma unroll
    for (int q = 0; q < 4; q++) v += g_part_proj[q * (Bb * Hh) + idx];
    float s = tanh_mufu(v);
    g_s[idx] = s;
    split_w(s, g_s_h, g_s_l, idx);
    g_y_h[idx] = __float2bfloat16(0.0f);
    g_y_l[idx] = __float2bfloat16(0.0f);
    if (idx < Bb) g_bsync[idx] = 0;
    if (idx == 0) { g_bar_count = 0; g_bar_gen = 0; }
}

// ---------------- zeta: out = softmax(tanh(pre)); updates y splits --------------
__device__ void zeta_phase(int b, int step, int par, const float* rnn_b_ih,
                           const float* rnn_b_hh, float* out, float* red, float* s_bc)
{
    const int tid = threadIdx.x;
    const int w = tid >> 5, l = tid & 31;
    const float* pp = g_part_pre + (long)par * 8 * BV;
    float4 acc = ((const float4*)rnn_b_ih)[tid];
    float4 b2  = ((const float4*)rnn_b_hh)[tid];
    acc.x += b2.x; acc.y += b2.y; acc.z += b2.z; acc.w += b2.w;
#pragma unroll
    for (int q = 0; q < 8; q++) {
        float4 p = ((const float4*)(pp + (long)q * BV + b * Vv))[tid];
        acc.x += p.x; acc.y += p.y; acc.z += p.z; acc.w += p.w;
    }
    float t0 = tanh_mufu(acc.x), t1 = tanh_mufu(acc.y);
    float t2 = tanh_mufu(acc.z), t3 = tanh_mufu(acc.w);
    float m = fmaxf(fmaxf(t0, t1), fmaxf(t2, t3));
    m = warp_max(m);
    if (l == 0) red[w] = m;
    __syncthreads();
    if (tid == 0) {
        float mm = red[0];
#pragma unroll
        for (int i = 1; i < 8; i++) mm = fmaxf(mm, red[i]);
        *s_bc = mm;
    }
    __syncthreads();
    float mx = *s_bc;
    float e0 = exp_mufu(t0 - mx), e1 = exp_mufu(t1 - mx);
    float e2 = exp_mufu(t2 - mx), e3 = exp_mufu(t3 - mx);
    float s = warp_sum(e0 + e1 + e2 + e3);
    if (l == 0) red[w] = s;
    __syncthreads();
    if (tid == 0) {
        float ss = 0.0f;
#pragma unroll
        for (int i = 0; i < 8; i++) ss += red[i];
        *s_bc = rcp_approx(ss);
    }
    __syncthreads();
    float inv = *s_bc;
    float y0 = e0 * inv, y1 = e1 * inv, y2 = e2 * inv, y3 = e3 * inv;
    long base = (long)b * 1024 + tid * 4;
    split_w(y0, g_y_h, g_y_l, base + 0);
    split_w(y1, g_y_h, g_y_l, base + 1);
    split_w(y2, g_y_h, g_y_l, base + 2);
    split_w(y3, g_y_h, g_y_l, base + 3);
    ((float4*)(out + ((long)b * Ss + step) * Vv))[tid] = make_float4(y0, y1, y2, y3);
    __syncthreads();
}

// ---------------- the persistent kernel -----------------------------------------
__global__ void __launch_bounds__(256, 2)
persist_kernel(const float* __restrict__ b_s_a, const float* __restrict__ w_a,
               const float* __restrict__ gru_b_ih, const float* __restrict__ gru_b_hh,
               const float* __restrict__ rnn_b_ih, const float* __restrict__ rnn_b_hh,
               float* __restrict__ out)
{
    __shared__ __align__(16) unsigned char sraw[sizeof(SmemTC)];
    __shared__ float s_bc;
    SmemTC* sm = (SmemTC*)sraw;
    float* p_sh = (float*)sraw;        // 1024 floats (proj; reused for ctx partials)
    float* w_sh = p_sh + 1024;         // 1024 (w_a)
    float* sc   = w_sh + 1024;         // 256 (softmax a)
    float* red  = sc + 256;            // 8

    const int blk = blockIdx.x;
    const int tid = threadIdx.x;
    const int w = tid >> 5, l = tid & 31;

    // ==== Phi0: proj for step 0 (blocks 0-63) + gh for step 0 (blocks 64-159)
    if (blk < 64) {
        int nt = blk >> 2, z = blk & 3;
        gemm_tc<false>(g_s_h + z * 256, g_s_l + z * 256, 1024,
                       g_wsa_h + (long)nt * 64 * 1024 + z * 256,
                       g_wsa_l + (long)nt * 64 * 1024 + z * 256, 1024,
                       256, g_part_proj + z * (Bb * Hh) + nt * 64, Hh, sm);
    } else if (blk < 160) {   // gh_0 = s0 @ gru_w_hh^T : 48nt x 2z, K=512
        int i = blk - 64, nt = i >> 1, z = i & 1;
        gemm_tc<false>(g_s_h + z * 512, g_s_l + z * 512, 1024,
                       g_gwh_h + (long)nt * 64 * 1024 + z * 512,
                       g_gwh_l + (long)nt * 64 * 1024 + z * 512, 1024,
                       512, g_part_gh + (long)z * (Bb * H3) + nt * 64, H3, sm);
    }
    grid_barrier();

    for (int step = 0; step < Ss; step++) {
        const int par = step & 1;

        // ==== Phi1: beta2 (blocks 0-255: pair (b, half)) || zeta_prev (256-295)
        if (blk < 256) {
            const int b = blk >> 1, half = blk & 1;
            {
                float4 acc = ((const float4*)b_s_a)[tid];
#pragma unroll
                for (int z = 0; z < 4; z++) {
                    float4 v = ((const float4*)(g_part_proj + z * (Bb * Hh) + b * Hh))[tid];
                    acc.x += v.x; acc.y += v.y; acc.z += v.z; acc.w += v.w;
                }
                ((float4*)p_sh)[tid] = acc;
                ((float4*)w_sh)[tid] = ((const float4*)w_a)[tid];
            }
            __syncthreads();
            // scores: STREAMING wh loads (evict-first; verified best in R13);
            // 8-deep load batching; all reductions deferred.
            {
                const uint4* whb4 = (const uint4*)(g_whb + (long)b * Tt * Hh);
                int t0 = half * 128 + w * 16;
                float a[16];
#pragma unroll
                for (int q = 0; q < 16; q++) a[q] = 0.0f;
#pragma unroll
                for (int tt8 = 0; tt8 < 16; tt8 += 8) {
                    int t = t0 + tt8;
#pragma unroll
                    for (int jj = 0; jj < 4; jj++) {
                        int fi = jj * 32 + l;
                        uint4 u[8];
#pragma unroll
                        for (int q = 0; q < 8; q++)
                            u[q] = ldg_ef(&whb4[(long)(t + q) * 128 + fi]);
                        float4 p0 = ((const float4*)p_sh)[fi * 2];
                        float4 p1 = ((const float4*)p_sh)[fi * 2 + 1];
                        float4 w0 = ((const float4*)w_sh)[fi * 2];
                        float4 w1 = ((const float4*)w_sh)[fi * 2 + 1];
#pragma unroll
                        for (int q = 0; q < 8; q++)
                            a[tt8 + q] += score8(u[q], p0, p1, w0, w1);
                    }
                }
#pragma unroll
                for (int q = 0; q < 16; q++) a[q] = warp_sum(a[q]);
                if (l == 0) {
#pragma unroll
                    for (int q = 0; q < 16; q++)
                        g_scores[b * Tt + t0 + q] = a[q];
                }
            }
            // per-b sync between the two halves (monotonic counter)
            __threadfence();
            __syncthreads();
            if (tid == 0) {
                atomicAdd(&g_bsync[b], 1u);
                unsigned target = 2u * (unsigned)(step + 1);
                while (*(volatile unsigned*)&g_bsync[b] < target) { }
                __threadfence();
            }
            __syncthreads();
            // softmax over all 256 scores (both blocks of the pair compute it)
            {
                float v = g_scores[b * Tt + tid];
                float m = warp_max(v);
                if (l == 0) red[w] = m;
                __syncthreads();
                if (tid == 0) {
                    float mm = red[0];
#pragma unroll
                    for (int i = 1; i < 8; i++) mm = fmaxf(mm, red[i]);
                    s_bc = mm;
                }
                __syncthreads();
                float e = exp_mufu(v - s_bc);
                float s = warp_sum(e);
                if (l == 0) red[w] = s;
                __syncthreads();
                if (tid == 0) {
                    float ss = 0.0f;
#pragma unroll
                    for (int i = 0; i < 8; i++) ss += red[i];
                    s_bc = rcp_approx(ss);
                }
                __syncthreads();
                sc[tid] = e * s_bc;
            }
            __syncthreads();
            // ctx: streaming loads, 8-deep batching
            {
                const int sub = tid >> 6, pos = tid & 63;
                const uint4* hp16 = (const uint4*)(g_hf16 + (long)b * Tt * Dd);
                float cr[8];
#pragma unroll
                for (int q = 0; q < 8; q++) cr[q] = 0.0f;
                for (int i = 0; i < 64; i += 8) {     // t = sub + 4*(i+j)
                    uint4 u[8];
                    float av[8];
#pragma unroll
                    for (int j = 0; j < 8; j++) {
                        int t = sub + 4 * (i + j);
                        u[j] = ldg_ef(&hp16[(long)t * 128 + half * 64 + pos]);
                        av[j] = sc[t];
                    }
#pragma unroll
                    for (int j = 0; j < 8; j++) {
                        __half2* hh2 = (__half2*)&u[j];
                        float a = av[j];
#pragma unroll
                        for (int q = 0; q < 4; q++) {
                            float2 f = __half22float2(hh2[q]);
                            cr[2*q]   = fmaf(a, f.x, cr[2*q]);
                            cr[2*q+1] = fmaf(a, f.y, cr[2*q+1]);
                        }
                    }
                }
                __syncthreads();      // p_sh/w_sh free now (scores done)
                float* part = p_sh;   // [4][512] = 2048 floats
#pragma unroll
                for (int q = 0; q < 8; q++) part[sub * 512 + pos * 8 + q] = cr[q];
                __syncthreads();
                long cb = (long)b * 1024 + half * 512;
#pragma unroll
                for (int r2 = 0; r2 < 2; r2++) {
                    int d = tid * 2 + r2;
                    float v = part[d] + part[512 + d] + part[1024 + d] + part[1536 + d];
                    split_w(v, g_c_h, g_c_l, cb + d);
                }
            }
        } else if (step > 0) {   // zeta for step-1: blocks 256-295 grid-stride
            for (int bb = blk - 256; bb < Bb; bb += 40)
                zeta_phase(bb, step - 1, par ^ 1, rnn_b_ih, rnn_b_hh, out, red, &s_bc);
        }
        grid_barrier();

        // ==== Phi2: gi_y(0-95) || gi_c(96-191) || pre_ih_c(192-223) || pre_hh(224-255)
        if (blk < 96) {
            int nt = blk >> 1, z = blk & 1;
            gemm_tc<false>(g_y_h + z * 512, g_y_l + z * 512, 1024,
                           g_gwi_h + (long)nt * 64 * 2048 + 1024 + z * 512,
                           g_gwi_l + (long)nt * 64 * 2048 + 1024 + z * 512, 2048,
                           512, g_part_gi + (long)z * (Bb * H3) + nt * 64, H3, sm);
        } else if (blk < 192) {
            int i = blk - 96, nt = i >> 1, z = i & 1;
            gemm_tc<false>(g_c_h + z * 512, g_c_l + z * 512, 1024,
                           g_gwi_h + (long)nt * 64 * 2048 + z * 512,
                           g_gwi_l + (long)nt * 64 * 2048 + z * 512, 2048,
                           512, g_part_gi + (long)(2 + z) * (Bb * H3) + nt * 64, H3, sm);
        } else if (blk < 224) {
            int i = blk - 192, nt = i >> 1, z = i & 1;
            gemm_tc<false>(g_c_h + z * 512, g_c_l + z * 512, 1024,
                           g_rwi_h + (long)nt * 64 * 2048 + z * 512,
                           g_rwi_l + (long)nt * 64 * 2048 + z * 512, 2048,
                           512, g_part_pre + ((long)par * 8 + z) * BV + nt * 64, Vv, sm);
        } else if (blk < 256) {
            int i = blk - 224, nt = i >> 1, z = i & 1;
            gemm_tc<false>(g_y_h + z * 512, g_y_l + z * 512, 1024,
                           g_rwh_h + (long)nt * 64 * 1024 + z * 512,
                           g_rwh_l + (long)nt * 64 * 1024 + z * 512, 1024,
                           512, g_part_pre + ((long)par * 8 + 6 + z) * BV + nt * 64, Vv, sm);
        }
        grid_barrier();

        // ==== Phi3: GRU elementwise
        for (int idx = blk * 256 + tid; idx < Bb * Hh; idx += NBLK * 256) {
            int b = idx >> 10, hh = idx & 1023;
            float gir = gru_b_ih[hh], giz = gru_b_ih[1024 + hh], gin = gru_b_ih[2048 + hh];
#pragma unroll
            for (int q = 0; q < 4; q++) {
                const float* p = g_part_gi + (long)(q * Bb + b) * H3 + hh;
                gir += p[0]; giz += p[1024]; gin += p[2048];
            }
            float ghr = gru_b_hh[hh], ghz = gru_b_hh[1024 + hh], ghn = gru_b_hh[2048 + hh];
#pragma unroll
            for (int q = 0; q < 2; q++) {
                const float* p = g_part_gh + (long)(q * Bb + b) * H3 + hh;
                ghr += p[0]; ghz += p[1024]; ghn += p[2048];
            }
            float r = sigmoid_mufu(gir + ghr);
            float z = sigmoid_mufu(giz + ghz);
            float n = tanh_mufu(fmaf(r, ghn, gin));
            float sv = g_s[idx];
            float sn = fmaf(z, sv - n, n);
            g_s[idx] = sn;
            split_w(sn, g_s_h, g_s_l, idx);
        }
        grid_barrier();

        // ==== Phi4: pre_ih_s(0-63, K=256) || proj_next(64-127, K=256) || gh_next(128-223, K=512)
        if (blk < 64) {
            int nt = blk >> 2, z = blk & 3;
            gemm_tc<false>(g_s_h + z * 256, g_s_l + z * 256, 1024,
                           g_rwi_h + (long)nt * 64 * 2048 + 1024 + z * 256,
                           g_rwi_l + (long)nt * 64 * 2048 + 1024 + z * 256, 2048,
                           256, g_part_pre + ((long)par * 8 + 2 + z) * BV + nt * 64, Vv, sm);
        } else if (blk < 128) {
            int i = blk - 64, nt = i >> 2, z = i & 3;
            gemm_tc<false>(g_s_h + z * 256, g_s_l + z * 256, 1024,
                           g_wsa_h + (long)nt * 64 * 1024 + z * 256,
                           g_wsa_l + (long)nt * 64 * 1024 + z * 256, 1024,
                           256, g_part_proj + z * (Bb * Hh) + nt * 64, Hh, sm);
        } else if (blk < 224) {
            int i = blk - 128, nt = i >> 1, z = i & 1;
            gemm_tc<false>(g_s_h + z * 512, g_s_l + z * 512, 1024,
                           g_gwh_h + (long)nt * 64 * 1024 + z * 512,
                           g_gwh_l + (long)nt * 64 * 1024 + z * 512, 1024,
                           512, g_part_gh + (long)z * (Bb * H3) + nt * 64, H3, sm);
        }
        grid_barrier();
    }
    // tail: zeta for the final step
    if (blk < 128) {
        zeta_phase(blk, Ss - 1, (Ss - 1) & 1, rnn_b_ih, rnn_b_hh, out, red, &s_bc);
    }
}

// ---------------- launcher -------------------------------------------------------
extern "C" void kernel_launch(void* const* d_in, const int* in_sizes, int n_in,
                              void* d_out, int out_size)
{
    const float* h        = (const float*)d_in[0];
    const float* w_h_a    = (const float*)d_in[1];
    const float* w_s_a    = (const float*)d_in[2];
    const float* b_s_a    = (const float*)d_in[3];
    const float* w_a      = (const float*)d_in[4];
    const float* w_init_s = (const float*)d_in[5];
    const float* b_init_s = (const float*)d_in[6];
    const float* gru_w_ih = (const float*)d_in[7];
    const float* gru_w_hh = (const float*)d_in[8];
    const float* gru_b_ih = (const float*)d_in[9];
    const float* gru_b_hh = (const float*)d_in[10];
    const float* rnn_w_ih = (const float*)d_in[11];
    const float* rnn_w_hh = (const float*)d_in[12];
    const float* rnn_b_ih = (const float*)d_in[13];
    const float* rnn_b_hh = (const float*)d_in[14];
    float* out = (float*)d_out;

    conv_all<<<2048, 256>>>(w_h_a, w_init_s, w_s_a, gru_w_hh, gru_w_ih,
                            rnn_w_ih, rnn_w_hh, h);
    prep_gemm_kernel<<<4160, 256>>>();
    init_state_kernel<<<512, 256>>>(b_init_s);
    persist_kernel<<<NBLK, 256>>>(b_s_a, w_a, gru_b_ih, gru_b_hh,
                                  rnn_b_ih, rnn_b_hh, out);
    (void)in_sizes; (void)n_in; (void)out_size;
}